// round 1
// baseline (speedup 1.0000x reference)
#include <cuda_runtime.h>

// HadamardTransform: y[b,:,h,w] = (H_1024 @ pad(x[b,:,h,w]))[0:768] / 32
// FWHT-1024 per pixel, warp-per-pixel, 32x32 register/shfl decomposition.

#define DIMC     768
#define NPIX     32          // pixels per CTA tile
#define PSTR     33          // smem row stride (floats), conflict-free
#define THREADS  1024
#define PIX_PER_IMG 3136     // 56*56
#define TILES_PER_IMG 98     // 3136/32

__global__ __launch_bounds__(THREADS, 1)
void fwht1024_kernel(const float* __restrict__ x, float* __restrict__ y) {
    extern __shared__ float s[];   // [768][33] floats = 101376 B

    const int tid = threadIdx.x;
    const int T   = blockIdx.x;
    const int b   = T / TILES_PER_IMG;
    const int p0  = (T % TILES_PER_IMG) * NPIX;
    const size_t base = (size_t)b * DIMC * PIX_PER_IMG + p0;

    // ---- Phase 1: coalesced float4 load of [768 x 32] tile into smem ----
    // 768 channels * 8 float4 = 6144 float4; 6 per thread.
    #pragma unroll
    for (int it = 0; it < 6; it++) {
        int f = it * THREADS + tid;       // 0..6143
        int c = f >> 3;                   // channel
        int q = f & 7;                    // float4 index within 32 pixels
        float4 v = *(const float4*)(x + base + (size_t)c * PIX_PER_IMG + q * 4);
        float* sr = s + c * PSTR + q * 4;
        sr[0] = v.x; sr[1] = v.y; sr[2] = v.z; sr[3] = v.w;
    }
    __syncthreads();

    // ---- Phase 2: warp-per-pixel FWHT-1024 ----
    const int lane = tid & 31;
    const int p    = tid >> 5;            // warp id == pixel within tile

    float v[32];
    // element index i = r*32 + lane ; channel c = i (zero for c >= 768)
    #pragma unroll
    for (int r = 0; r < 24; r++)
        v[r] = s[(r * 32 + lane) * PSTR + p];
    #pragma unroll
    for (int r = 24; r < 32; r++)
        v[r] = 0.0f;

    // 5 butterfly stages over the register-index bits
    #pragma unroll
    for (int st = 0; st < 5; st++) {
        const int m = 1 << st;
        #pragma unroll
        for (int r = 0; r < 32; r++) {
            if (!(r & m)) {
                float a = v[r], c2 = v[r + m];
                v[r]     = a + c2;
                v[r + m] = a - c2;
            }
        }
    }

    // 5 butterfly stages over the lane bits via shfl_xor
    #pragma unroll
    for (int st = 0; st < 5; st++) {
        const int m = 1 << st;
        const float sg = (lane & m) ? -1.0f : 1.0f;
        #pragma unroll
        for (int r = 0; r < 32; r++) {
            float t = __shfl_xor_sync(0xffffffffu, v[r], m);
            v[r] = fmaf(sg, v[r], t);     // lane-bit clear: v+t ; set: t-v
        }
    }

    // ---- Phase 3: scaled writeback of first 768 outputs to smem ----
    __syncthreads();   // everyone done reading smem before overwrite
    const float scale = 1.0f / 32.0f;
    #pragma unroll
    for (int r = 0; r < 24; r++)
        s[(r * 32 + lane) * PSTR + p] = v[r] * scale;
    __syncthreads();

    // ---- Phase 4: coalesced float4 store ----
    #pragma unroll
    for (int it = 0; it < 6; it++) {
        int f = it * THREADS + tid;
        int c = f >> 3;
        int q = f & 7;
        const float* sr = s + c * PSTR + q * 4;
        float4 v4 = make_float4(sr[0], sr[1], sr[2], sr[3]);
        *(float4*)(y + base + (size_t)c * PIX_PER_IMG + q * 4) = v4;
    }
}

extern "C" void kernel_launch(void* const* d_in, const int* in_sizes, int n_in,
                              void* d_out, int out_size) {
    (void)in_sizes; (void)n_in; (void)out_size;
    const float* x = (const float*)d_in[0];
    float* y = (float*)d_out;

    const int smem_bytes = DIMC * PSTR * sizeof(float);   // 101376
    cudaFuncSetAttribute(fwht1024_kernel,
                         cudaFuncAttributeMaxDynamicSharedMemorySize, smem_bytes);

    const int grid = 16 * TILES_PER_IMG;   // 1568 tiles
    fwht1024_kernel<<<grid, THREADS, smem_bytes>>>(x, y);
}